// round 2
// baseline (speedup 1.0000x reference)
#include <cuda_runtime.h>
#include <math.h>

// Fixed problem shape: B=2, CIN=64, COUT=128, E=100000.
#define EMAXV 100000

// Scratch (device globals: no allocation allowed in kernel_launch)
__device__ float g_feT [(size_t)2 * EMAXV * 64];    //  51 MB  fe transposed [B,E,64]
__device__ float g_x1T [(size_t)2 * EMAXV * 128];   // 102 MB  x1 transposed [B,E,128]
__device__ float g_x1cm[(size_t)2 * EMAXV * 128];   // 102 MB  x1 channel-major [B,128,E]
__device__ float g_y   [(size_t)2 * EMAXV * 128];   // 102 MB  conv output buffer
__device__ float g_w1T [320 * 128];
__device__ float g_w2T [640 * 128];
__device__ float g_stats[1024];                     // [mean(256), rstd(256)] x 2 convs

// ---------------------------------------------------------------------------
// Transpose x [B,C,E] -> xT [B,E,C]   (32x32 smem tiles)
// ---------------------------------------------------------------------------
__global__ void k_transpose_in(const float* __restrict__ x, float* __restrict__ xT,
                               int C, int E) {
    __shared__ float tile[32][33];
    int b  = blockIdx.z;
    int c0 = blockIdx.y * 32;
    int e0 = blockIdx.x * 32;
    int tx = threadIdx.x, ty = threadIdx.y;
#pragma unroll
    for (int r = ty; r < 32; r += 8) {
        int c = c0 + r, e = e0 + tx;
        float v = 0.f;
        if (e < E) v = x[((size_t)b * C + c) * E + e];
        tile[r][tx] = v;
    }
    __syncthreads();
#pragma unroll
    for (int r = ty; r < 32; r += 8) {
        int e = e0 + r, c = c0 + tx;
        if (e < E) xT[((size_t)b * E + e) * C + c] = tile[tx][r];
    }
}

// ---------------------------------------------------------------------------
// Transpose weights w [128,K] -> wT [K,128]  (tiny)
// ---------------------------------------------------------------------------
__global__ void k_transpose_w(const float* __restrict__ w, float* __restrict__ wt, int K) {
    int i = blockIdx.x * 256 + threadIdx.x;
    if (i < K * 128) {
        int k = i >> 7, o = i & 127;
        wt[i] = w[o * K + k];
    }
}

// ---------------------------------------------------------------------------
// Fused gather + symmetric-feature build + GEMM:
//   y[b, o, e] = sum_{c,s} W[o, c*5+s] * Gm[c*5+s, e]
// Block tile: M=128 (all Cout) x TE=128 edges; K chunks of 40 (8 ch x 5 feat).
// Thread tile: 4m x 16e (64 accum). Gm reads are warp-broadcast (conflict-free).
// Bias omitted: InstanceNorm immediately follows, bias cancels exactly.
// ---------------------------------------------------------------------------
template <int CIN>
__global__ void __launch_bounds__(256, 2) k_conv(
    const float* __restrict__ xT,    // [B,E,CIN]
    const int*   __restrict__ gmm,   // [B,E,4]
    const float* __restrict__ WT,    // [5*CIN, 128]
    float*       __restrict__ y,     // [B,128,E]
    int E)
{
    constexpr int KC  = 40;          // K-chunk = 8 channels * 5 features
    constexpr int NCH = CIN / 8;     // number of chunks
    __shared__ float Ws[KC * 128];
    __shared__ float Gm[KC * 132];   // pad 128->132 floats: conflict-free stores

    const int tid = threadIdx.x;
    const int b   = blockIdx.y;
    const int e0  = blockIdx.x * 128;

    // ---- gather setup: 2 threads per edge, each owns 4 channels per chunk ----
    const int eloc = tid >> 1;       // 0..127 local edge
    const int half = tid & 1;        // channel half within 8-channel chunk
    int eg = e0 + eloc;
    if (eg >= E) eg = 0;             // clamp (results discarded by store guard)
    const size_t brow = (size_t)b * E;
    const float *bp0, *bp1, *bp2, *bp3, *bp4;
    {
        int4 nb = *reinterpret_cast<const int4*>(gmm + (brow + eg) * 4);
        bp0 = xT + (brow + eg)   * CIN;
        bp1 = xT + (brow + nb.x) * CIN;
        bp2 = xT + (brow + nb.y) * CIN;
        bp3 = xT + (brow + nb.z) * CIN;
        bp4 = xT + (brow + nb.w) * CIN;
    }

    // ---- GEMM thread mapping: m = tm*4 (+0..3),  e = tg*16 (+0..15) ----
    const int tm = tid & 31;
    const int tg = tid >> 5;

    float acc[4][16];
#pragma unroll
    for (int i = 0; i < 4; i++)
#pragma unroll
        for (int j = 0; j < 16; j++) acc[i][j] = 0.f;

    for (int ch = 0; ch < NCH; ++ch) {
        // load W chunk (coalesced): 40*128 floats = 1280 float4, 5 per thread
        {
            const float4* wg  = reinterpret_cast<const float4*>(WT + ch * KC * 128);
            float4*       ws4 = reinterpret_cast<float4*>(Ws);
#pragma unroll
            for (int i = 0; i < 5; ++i) ws4[tid + 256 * i] = wg[tid + 256 * i];
        }

        // gather 5 neighbor float4s (L2-resident), build symmetric features
        const int c0 = ch * 8 + half * 4;
        float4 q0 = *reinterpret_cast<const float4*>(bp0 + c0);
        float4 q1 = *reinterpret_cast<const float4*>(bp1 + c0);
        float4 q2 = *reinterpret_cast<const float4*>(bp2 + c0);
        float4 q3 = *reinterpret_cast<const float4*>(bp3 + c0);
        float4 q4 = *reinterpret_cast<const float4*>(bp4 + c0);
        float a0[4] = {q0.x, q0.y, q0.z, q0.w};
        float a1[4] = {q1.x, q1.y, q1.z, q1.w};
        float a2[4] = {q2.x, q2.y, q2.z, q2.w};
        float a3[4] = {q3.x, q3.y, q3.z, q3.w};
        float a4[4] = {q4.x, q4.y, q4.z, q4.w};
#pragma unroll
        for (int u = 0; u < 4; ++u) {
            int kk = (half * 4 + u) * 5;
            float* gp = Gm + kk * 132 + eloc;
            gp[0]       = a0[u];
            gp[132]     = a1[u] + a3[u];
            gp[132 * 2] = a2[u] + a4[u];
            gp[132 * 3] = fabsf(a1[u] - a3[u]);
            gp[132 * 4] = fabsf(a2[u] - a4[u]);
        }
        __syncthreads();

        // GEMM over this K chunk
#pragma unroll 4
        for (int kk = 0; kk < KC; ++kk) {
            float4 w = reinterpret_cast<const float4*>(Ws + kk * 128)[tm];
            const float* gr = Gm + kk * 132 + tg * 16;
            float4 g0 = reinterpret_cast<const float4*>(gr)[0];
            float4 g1 = reinterpret_cast<const float4*>(gr)[1];
            float4 g2 = reinterpret_cast<const float4*>(gr)[2];
            float4 g3 = reinterpret_cast<const float4*>(gr)[3];
            float wv[4]  = {w.x, w.y, w.z, w.w};
            float gv[16] = {g0.x, g0.y, g0.z, g0.w,
                            g1.x, g1.y, g1.z, g1.w,
                            g2.x, g2.y, g2.z, g2.w,
                            g3.x, g3.y, g3.z, g3.w};
#pragma unroll
            for (int i = 0; i < 4; i++)
#pragma unroll
                for (int j = 0; j < 16; j++)
                    acc[i][j] = fmaf(wv[i], gv[j], acc[i][j]);
        }
        __syncthreads();
    }

    // ---- write out [B,128,E] ----
    const int ebase = e0 + tg * 16;
#pragma unroll
    for (int i = 0; i < 4; ++i) {
        int m = tm * 4 + i;
        float* row = y + ((size_t)b * 128 + m) * E;
#pragma unroll
        for (int j4 = 0; j4 < 4; ++j4) {
            int e = ebase + j4 * 4;
            if (e < E) {
                float4 v = make_float4(acc[i][j4 * 4],     acc[i][j4 * 4 + 1],
                                       acc[i][j4 * 4 + 2], acc[i][j4 * 4 + 3]);
                *reinterpret_cast<float4*>(row + e) = v;
            }
        }
    }
}

// ---------------------------------------------------------------------------
// Per-(b,c) mean / rstd over E.  One block per row (256 rows).
// stats layout relative to passed pointer: [0..255]=mean, [256..511]=rstd
// ---------------------------------------------------------------------------
__global__ void k_rowstat(const float* __restrict__ y, float* __restrict__ stats, int E) {
    int row = blockIdx.x;
    const float4* p = reinterpret_cast<const float4*>(y + (size_t)row * E);
    int n4 = E >> 2;
    float s = 0.f, ss = 0.f;
    for (int i = threadIdx.x; i < n4; i += blockDim.x) {
        float4 v = p[i];
        s  += v.x + v.y + v.z + v.w;
        ss += v.x * v.x + v.y * v.y + v.z * v.z + v.w * v.w;
    }
    __shared__ float shs[16], shss[16];
    const unsigned mask = 0xffffffffu;
#pragma unroll
    for (int o = 16; o > 0; o >>= 1) {
        s  += __shfl_down_sync(mask, s, o);
        ss += __shfl_down_sync(mask, ss, o);
    }
    int w = threadIdx.x >> 5, l = threadIdx.x & 31;
    if (l == 0) { shs[w] = s; shss[w] = ss; }
    __syncthreads();
    if (w == 0) {
        s  = (l < 16) ? shs[l]  : 0.f;
        ss = (l < 16) ? shss[l] : 0.f;
#pragma unroll
        for (int o = 8; o > 0; o >>= 1) {
            s  += __shfl_down_sync(mask, s, o);
            ss += __shfl_down_sync(mask, ss, o);
        }
        if (l == 0) {
            float inv = 1.f / (float)E;
            float m   = s * inv;
            float var = fmaxf(ss * inv - m * m, 0.f);
            stats[row]       = m;
            stats[256 + row] = rsqrtf(var + 1e-5f);
        }
    }
}

// ---------------------------------------------------------------------------
// x1 = relu(instnorm(y)); write both channel-major copy and [B,E,128] transpose
// ---------------------------------------------------------------------------
__global__ void k_norm_relu_tr(const float* __restrict__ y, const float* __restrict__ stats,
                               float* __restrict__ xcm, float* __restrict__ xT, int E) {
    __shared__ float tile[32][33];
    int b  = blockIdx.z;
    int c0 = blockIdx.y * 32;
    int e0 = blockIdx.x * 32;
    int tx = threadIdx.x, ty = threadIdx.y;
#pragma unroll
    for (int r = ty; r < 32; r += 8) {
        int c = c0 + r, e = e0 + tx;
        int rowi = b * 128 + c;
        float v = 0.f;
        if (e < E) {
            v = y[(size_t)rowi * E + e];
            v = (v - stats[rowi]) * stats[256 + rowi];
            v = fmaxf(v, 0.f);
            xcm[(size_t)rowi * E + e] = v;
        }
        tile[r][tx] = v;
    }
    __syncthreads();
#pragma unroll
    for (int r = ty; r < 32; r += 8) {
        int e = e0 + r, c = c0 + tx;
        if (e < E) xT[((size_t)b * E + e) * 128 + c] = tile[tx][r];
    }
}

// ---------------------------------------------------------------------------
// out = relu(instnorm(y2) + x1)
// ---------------------------------------------------------------------------
__global__ void k_final(const float* __restrict__ y, const float* __restrict__ stats,
                        const float* __restrict__ xcm, float* __restrict__ out, int E) {
    int n4row = E >> 2;
    int total = 256 * n4row;
    int i = blockIdx.x * blockDim.x + threadIdx.x;
    if (i >= total) return;
    int row = i / n4row;
    float m = stats[row], r = stats[256 + row];
    float4 v = reinterpret_cast<const float4*>(y)[i];
    float4 a = reinterpret_cast<const float4*>(xcm)[i];
    float4 o;
    o.x = fmaxf((v.x - m) * r + a.x, 0.f);
    o.y = fmaxf((v.y - m) * r + a.y, 0.f);
    o.z = fmaxf((v.z - m) * r + a.z, 0.f);
    o.w = fmaxf((v.w - m) * r + a.w, 0.f);
    reinterpret_cast<float4*>(out)[i] = o;
}

// ---------------------------------------------------------------------------
extern "C" void kernel_launch(void* const* d_in, const int* in_sizes, int n_in,
                              void* d_out, int out_size) {
    const float* fe = (const float*)d_in[0];
    const int*   gm = (const int*)d_in[1];
    const float* w1 = (const float*)d_in[2];
    // d_in[3] = b1, d_in[5] = b2: unused — InstanceNorm cancels conv bias exactly.
    const float* w2 = (const float*)d_in[4];
    float* out = (float*)d_out;

    const int B = 2, CIN = 64;
    int E = in_sizes[0] / (B * CIN);   // 100000

    float *feT, *x1T, *x1cm, *ybuf, *w1T, *w2T, *stats;
    cudaGetSymbolAddress((void**)&feT,   g_feT);
    cudaGetSymbolAddress((void**)&x1T,   g_x1T);
    cudaGetSymbolAddress((void**)&x1cm,  g_x1cm);
    cudaGetSymbolAddress((void**)&ybuf,  g_y);
    cudaGetSymbolAddress((void**)&w1T,   g_w1T);
    cudaGetSymbolAddress((void**)&w2T,   g_w2T);
    cudaGetSymbolAddress((void**)&stats, g_stats);

    int eT32  = (E + 31) / 32;
    int eT128 = (E + 127) / 128;

    k_transpose_w<<<(320 * 128 + 255) / 256, 256>>>(w1, w1T, 320);
    k_transpose_w<<<(640 * 128 + 255) / 256, 256>>>(w2, w2T, 640);
    k_transpose_in<<<dim3(eT32, 2, 2), dim3(32, 8)>>>(fe, feT, 64, E);

    k_conv<64><<<dim3(eT128, 2), 256>>>(feT, gm, w1T, ybuf, E);
    k_rowstat<<<256, 512>>>(ybuf, stats, E);
    k_norm_relu_tr<<<dim3(eT32, 4, 2), dim3(32, 8)>>>(ybuf, stats, x1cm, x1T, E);

    k_conv<128><<<dim3(eT128, 2), 256>>>(x1T, gm, w2T, ybuf, E);
    k_rowstat<<<256, 512>>>(ybuf, stats + 512, E);

    int total4 = 256 * (E >> 2);
    k_final<<<(total4 + 255) / 256, 256>>>(ybuf, stats + 512, x1cm, out, E);
}

// round 4
// speedup vs baseline: 2.0262x; 2.0262x over previous
#include <cuda_runtime.h>
#include <math.h>
#include <cstdint>

// Fixed problem shape: B=2, CIN=64, COUT=128, E=100000.
#define EMAXV 100000

// Scratch (device globals: no allocation allowed in kernel_launch)
__device__ float g_feT [(size_t)2 * EMAXV * 64];    // fe transposed [B,E,64]
__device__ float g_x1T [(size_t)2 * EMAXV * 128];   // x1 transposed [B,E,128]
__device__ float g_x1cm[(size_t)2 * EMAXV * 128];   // x1 channel-major [B,128,E]
__device__ float g_y   [(size_t)2 * EMAXV * 128];   // conv output buffer
__device__ float g_w1p [40960];                     // W1 in mma-fragment order (tf32)
__device__ float g_w2p [81920];                     // W2 in mma-fragment order (tf32)
__device__ float g_stats[1024];

__device__ __forceinline__ float to_tf32(float x) {
    float r;
    asm("cvt.rna.tf32.f32 %0, %1;" : "=f"(r) : "f"(x));
    return r;
}

// ---------------------------------------------------------------------------
// Transpose x [B,C,E] -> xT [B,E,C]
// ---------------------------------------------------------------------------
__global__ void k_transpose_in(const float* __restrict__ x, float* __restrict__ xT,
                               int C, int E) {
    __shared__ float tile[32][33];
    int b  = blockIdx.z;
    int c0 = blockIdx.y * 32;
    int e0 = blockIdx.x * 32;
    int tx = threadIdx.x, ty = threadIdx.y;
#pragma unroll
    for (int r = ty; r < 32; r += 8) {
        int c = c0 + r, e = e0 + tx;
        float v = 0.f;
        if (e < E) v = x[((size_t)b * C + c) * E + e];
        tile[r][tx] = v;
    }
    __syncthreads();
#pragma unroll
    for (int r = ty; r < 32; r += 8) {
        int e = e0 + r, c = c0 + tx;
        if (e < E) xT[((size_t)b * E + e) * C + c] = tile[tx][r];
    }
}

// ---------------------------------------------------------------------------
// Weight prep: w [128, CIN, 5] -> per-(chunk,warp,kstep,frag,lane,q) tf32 frags.
// Layout: ((((ci*2+wm)*5+ks)*4+mf)*32+lane)*4+q  where q = a0..a3 of the
// m16n8k8 A fragment:
//   m = wm*64 + mf*16 + (lane>>2) + (q&1)*8
//   k_in_chunk = ks*8 + (lane&3) + ((q>>1)&1)*4 ;  c = ci*8 + k/5 ; s = k%5
// ---------------------------------------------------------------------------
__global__ void k_wprep(const float* __restrict__ w, float* __restrict__ wp, int CIN) {
    int NCH = CIN / 8;
    int total = NCH * 5120;
    int i = blockIdx.x * 256 + threadIdx.x;
    if (i >= total) return;
    int q    = i & 3;
    int lane = (i >> 2) & 31;
    int mf   = (i >> 7) & 3;
    int ks   = (i >> 9) % 5;
    int wm   = (i / 2560) & 1;
    int ci   = i / 5120;
    int g = lane >> 2, t = lane & 3;
    int m  = wm * 64 + mf * 16 + g + (q & 1) * 8;
    int kc = ks * 8 + t + ((q >> 1) & 1) * 4;
    int c  = ci * 8 + kc / 5;
    int s  = kc % 5;
    wp[i] = to_tf32(w[m * (CIN * 5) + c * 5 + s]);
}

// ---------------------------------------------------------------------------
// Fused gather + symmetric features + tensor-core GEMM (mma.sync tf32):
//   y[b, 0..127, e0..e0+127] = W[128, 5*CIN] x Gm[5*CIN, 128-edge tile]
// 8 warps, 2x4 warp grid, warp tile 64x32. K chunks of 40 (8 ch x 5 feats).
// Gm in smem edge-major [128][44] (pad 44 -> conflict-free frag loads).
// A fragments come pre-arranged from global (coalesced float4, L1-resident).
// Bias omitted: InstanceNorm cancels it exactly.
// ---------------------------------------------------------------------------
template <int CIN>
__global__ void __launch_bounds__(256, 2) k_conv_mma(
    const float* __restrict__ xT,    // [B,E,CIN]
    const int*   __restrict__ gmm,   // [B,E,4]
    const float* __restrict__ Wp,    // fragment-ordered tf32 weights
    float*       __restrict__ y,     // [B,128,E]
    int E)
{
    constexpr int NCH = CIN / 8;
    __shared__ float Gm[128 * 44];
    __shared__ int4  nbr[128];

    const int tid  = threadIdx.x;
    const int wid  = tid >> 5, lane = tid & 31;
    const int b    = blockIdx.y;
    const int e0   = blockIdx.x * 128;
    const size_t brow = (size_t)b * E;

    if (tid < 128) {
        int e = e0 + tid; if (e >= E) e = 0;
        nbr[tid] = ((const int4*)gmm)[brow + e];
    }
    __syncthreads();

    // gather roles: 2 threads per edge, each owns 4 channels per chunk
    const int eloc = tid >> 1;
    const int half = tid & 1;
    int eg = e0 + eloc; if (eg >= E) eg = 0;
    const int4 nb = nbr[eloc];
    const float* p0 = xT + (brow + eg)   * CIN;
    const float* p1 = xT + (brow + nb.x) * CIN;
    const float* p2 = xT + (brow + nb.y) * CIN;
    const float* p3 = xT + (brow + nb.z) * CIN;
    const float* p4 = xT + (brow + nb.w) * CIN;

    // mma roles
    const int wm = wid & 1;       // 2: M halves of 64
    const int wn = wid >> 1;      // 4: N blocks of 32
    const int g  = lane >> 2, t = lane & 3;

    float acc[4][4][4];
#pragma unroll
    for (int i = 0; i < 4; i++)
#pragma unroll
        for (int j = 0; j < 4; j++)
#pragma unroll
            for (int k = 0; k < 4; k++) acc[i][j][k] = 0.f;

    for (int ch = 0; ch < NCH; ++ch) {
        // ---- build Gm chunk: 40 k-rows (8 channels x 5 features) ----
        const int c0 = ch * 8 + half * 4;
        float4 q0 = *(const float4*)(p0 + c0);
        float4 q1 = *(const float4*)(p1 + c0);
        float4 q2 = *(const float4*)(p2 + c0);
        float4 q3 = *(const float4*)(p3 + c0);
        float4 q4 = *(const float4*)(p4 + c0);
        float a0[4] = {q0.x, q0.y, q0.z, q0.w};
        float a1[4] = {q1.x, q1.y, q1.z, q1.w};
        float a2[4] = {q2.x, q2.y, q2.z, q2.w};
        float a3[4] = {q3.x, q3.y, q3.z, q3.w};
        float a4[4] = {q4.x, q4.y, q4.z, q4.w};
        {
            float* gp = Gm + eloc * 44 + half * 20;
#pragma unroll
            for (int u = 0; u < 4; ++u) {
                gp[u * 5 + 0] = to_tf32(a0[u]);
                gp[u * 5 + 1] = to_tf32(a1[u] + a3[u]);
                gp[u * 5 + 2] = to_tf32(a2[u] + a4[u]);
                gp[u * 5 + 3] = to_tf32(fabsf(a1[u] - a3[u]));
                gp[u * 5 + 4] = to_tf32(fabsf(a2[u] - a4[u]));
            }
        }
        __syncthreads();

        // ---- mma over 5 k8-steps ----
        const float* wbase = Wp + (size_t)(ch * 2 + wm) * 2560;
#pragma unroll
        for (int ks = 0; ks < 5; ++ks) {
            uint32_t A[4][4];
#pragma unroll
            for (int mf = 0; mf < 4; ++mf) {
                float4 v = ((const float4*)(wbase + (ks * 4 + mf) * 128))[lane];
                A[mf][0] = __float_as_uint(v.x);
                A[mf][1] = __float_as_uint(v.y);
                A[mf][2] = __float_as_uint(v.z);
                A[mf][3] = __float_as_uint(v.w);
            }
            uint32_t Bf[4][2];
#pragma unroll
            for (int nf = 0; nf < 4; ++nf) {
                const float* bp = Gm + (wn * 32 + nf * 8 + g) * 44 + ks * 8 + t;
                Bf[nf][0] = __float_as_uint(bp[0]);
                Bf[nf][1] = __float_as_uint(bp[4]);
            }
#pragma unroll
            for (int mf = 0; mf < 4; ++mf)
#pragma unroll
                for (int nf = 0; nf < 4; ++nf) {
                    asm volatile(
                        "mma.sync.aligned.m16n8k8.row.col.f32.tf32.tf32.f32 "
                        "{%0,%1,%2,%3}, {%4,%5,%6,%7}, {%8,%9}, {%0,%1,%2,%3};\n"
                        : "+f"(acc[mf][nf][0]), "+f"(acc[mf][nf][1]),
                          "+f"(acc[mf][nf][2]), "+f"(acc[mf][nf][3])
                        : "r"(A[mf][0]), "r"(A[mf][1]), "r"(A[mf][2]), "r"(A[mf][3]),
                          "r"(Bf[nf][0]), "r"(Bf[nf][1]));
                }
        }
        __syncthreads();
    }

    // ---- epilogue: fragments -> y [B,128,E] ----
#pragma unroll
    for (int mf = 0; mf < 4; ++mf) {
        int m = wm * 64 + mf * 16 + g;
#pragma unroll
        for (int nf = 0; nf < 4; ++nf) {
            int n = e0 + wn * 32 + nf * 8 + t * 2;
            if (n < E) {
                float* r0 = y + ((size_t)b * 128 + m) * E + n;
                float* r1 = r0 + (size_t)8 * E;
                *(float2*)r0 = make_float2(acc[mf][nf][0], acc[mf][nf][1]);
                *(float2*)r1 = make_float2(acc[mf][nf][2], acc[mf][nf][3]);
            }
        }
    }
}

// ---------------------------------------------------------------------------
// Per-(b,c) mean / rstd over E.
// ---------------------------------------------------------------------------
__global__ void k_rowstat(const float* __restrict__ y, float* __restrict__ stats, int E) {
    int row = blockIdx.x;
    const float4* p = reinterpret_cast<const float4*>(y + (size_t)row * E);
    int n4 = E >> 2;
    float s = 0.f, ss = 0.f;
    for (int i = threadIdx.x; i < n4; i += blockDim.x) {
        float4 v = p[i];
        s  += v.x + v.y + v.z + v.w;
        ss += v.x * v.x + v.y * v.y + v.z * v.z + v.w * v.w;
    }
    __shared__ float shs[16], shss[16];
    const unsigned mask = 0xffffffffu;
#pragma unroll
    for (int o = 16; o > 0; o >>= 1) {
        s  += __shfl_down_sync(mask, s, o);
        ss += __shfl_down_sync(mask, ss, o);
    }
    int w = threadIdx.x >> 5, l = threadIdx.x & 31;
    if (l == 0) { shs[w] = s; shss[w] = ss; }
    __syncthreads();
    if (w == 0) {
        s  = (l < 16) ? shs[l]  : 0.f;
        ss = (l < 16) ? shss[l] : 0.f;
#pragma unroll
        for (int o = 8; o > 0; o >>= 1) {
            s  += __shfl_down_sync(mask, s, o);
            ss += __shfl_down_sync(mask, ss, o);
        }
        if (l == 0) {
            float inv = 1.f / (float)E;
            float mu  = s * inv;
            float var = fmaxf(ss * inv - mu * mu, 0.f);
            stats[row]       = mu;
            stats[256 + row] = rsqrtf(var + 1e-5f);
        }
    }
}

// ---------------------------------------------------------------------------
// x1 = relu(instnorm(y)); write channel-major copy and [B,E,128] transpose
// ---------------------------------------------------------------------------
__global__ void k_norm_relu_tr(const float* __restrict__ y, const float* __restrict__ stats,
                               float* __restrict__ xcm, float* __restrict__ xT, int E) {
    __shared__ float tile[32][33];
    int b  = blockIdx.z;
    int c0 = blockIdx.y * 32;
    int e0 = blockIdx.x * 32;
    int tx = threadIdx.x, ty = threadIdx.y;
#pragma unroll
    for (int r = ty; r < 32; r += 8) {
        int c = c0 + r, e = e0 + tx;
        int rowi = b * 128 + c;
        float v = 0.f;
        if (e < E) {
            v = y[(size_t)rowi * E + e];
            v = (v - stats[rowi]) * stats[256 + rowi];
            v = fmaxf(v, 0.f);
            xcm[(size_t)rowi * E + e] = v;
        }
        tile[r][tx] = v;
    }
    __syncthreads();
#pragma unroll
    for (int r = ty; r < 32; r += 8) {
        int e = e0 + r, c = c0 + tx;
        if (e < E) xT[((size_t)b * E + e) * 128 + c] = tile[tx][r];
    }
}

// ---------------------------------------------------------------------------
// out = relu(instnorm(y2) + x1)
// ---------------------------------------------------------------------------
__global__ void k_final(const float* __restrict__ y, const float* __restrict__ stats,
                        const float* __restrict__ xcm, float* __restrict__ out, int E) {
    int n4row = E >> 2;
    int total = 256 * n4row;
    int i = blockIdx.x * blockDim.x + threadIdx.x;
    if (i >= total) return;
    int row = i / n4row;
    float mu = stats[row], r = stats[256 + row];
    float4 v = reinterpret_cast<const float4*>(y)[i];
    float4 a = reinterpret_cast<const float4*>(xcm)[i];
    float4 o;
    o.x = fmaxf((v.x - mu) * r + a.x, 0.f);
    o.y = fmaxf((v.y - mu) * r + a.y, 0.f);
    o.z = fmaxf((v.z - mu) * r + a.z, 0.f);
    o.w = fmaxf((v.w - mu) * r + a.w, 0.f);
    reinterpret_cast<float4*>(out)[i] = o;
}

// ---------------------------------------------------------------------------
extern "C" void kernel_launch(void* const* d_in, const int* in_sizes, int n_in,
                              void* d_out, int out_size) {
    const float* fe = (const float*)d_in[0];
    const int*   gm = (const int*)d_in[1];
    const float* w1 = (const float*)d_in[2];
    // b1 (d_in[3]) and b2 (d_in[5]) unused: InstanceNorm cancels conv bias.
    const float* w2 = (const float*)d_in[4];
    float* out = (float*)d_out;

    const int B = 2, CIN = 64;
    int E = in_sizes[0] / (B * CIN);   // 100000

    float *feT, *x1T, *x1cm, *ybuf, *w1p, *w2p, *stats;
    cudaGetSymbolAddress((void**)&feT,   g_feT);
    cudaGetSymbolAddress((void**)&x1T,   g_x1T);
    cudaGetSymbolAddress((void**)&x1cm,  g_x1cm);
    cudaGetSymbolAddress((void**)&ybuf,  g_y);
    cudaGetSymbolAddress((void**)&w1p,   g_w1p);
    cudaGetSymbolAddress((void**)&w2p,   g_w2p);
    cudaGetSymbolAddress((void**)&stats, g_stats);

    int eT32  = (E + 31) / 32;
    int eT128 = (E + 127) / 128;

    k_wprep<<<(40960 + 255) / 256, 256>>>(w1, w1p, 64);
    k_wprep<<<(81920 + 255) / 256, 256>>>(w2, w2p, 128);
    k_transpose_in<<<dim3(eT32, 2, 2), dim3(32, 8)>>>(fe, feT, 64, E);

    k_conv_mma<64><<<dim3(eT128, 2), 256>>>(feT, gm, w1p, ybuf, E);
    k_rowstat<<<256, 512>>>(ybuf, stats, E);
    k_norm_relu_tr<<<dim3(eT32, 4, 2), dim3(32, 8)>>>(ybuf, stats, x1cm, x1T, E);

    k_conv_mma<128><<<dim3(eT128, 2), 256>>>(x1T, gm, w2p, ybuf, E);
    k_rowstat<<<256, 512>>>(ybuf, stats + 512, E);

    int total4 = 256 * (E >> 2);
    k_final<<<(total4 + 255) / 256, 256>>>(ybuf, stats + 512, x1cm, out, E);
}